// round 1
// baseline (speedup 1.0000x reference)
#include <cuda_runtime.h>
#include <cstdint>

#define NMAX 50000
#define EMAX 800000
#define H 64

// Scratch (no dynamic allocation allowed)
__device__ float g_g[NMAX * H];      // pre-scaled features g = (X@W)*dinv
__device__ float g_acc[NMAX * H];    // aggregation accumulator (init = g, self-loop)
__device__ int   g_deg[NMAX];
__device__ float g_dinv[NMAX];
__device__ int   g_src[EMAX];
__device__ int   g_dst[EMAX];
__device__ float g_colsum[H];
__device__ int   g_is64;

// ---------------------------------------------------------------------------
// Detect whether edge_index arrived as int64 (JAX x64 on) or int32 (x64 off).
// For int64 with values in [0, 50000), every odd 32-bit word is 0.
// For int32 random values, P(64 consecutive odd words all zero) ~ 0.
// ---------------------------------------------------------------------------
__global__ void detect_kernel(const unsigned int* __restrict__ w) {
    if (threadIdx.x == 0 && blockIdx.x == 0) {
        int all_zero = 1;
        for (int i = 0; i < 64; i++) {
            if (w[2 * i + 1] != 0u) { all_zero = 0; break; }
        }
        g_is64 = all_zero;
    }
}

__global__ void init_kernel(int N) {
    int i = blockIdx.x * blockDim.x + threadIdx.x;
    if (i < N) g_deg[i] = 1;           // self loop
    if (i < H) g_colsum[i] = 0.f;
}

__global__ void prep_edges(const int* __restrict__ ei, int E) {
    int e = blockIdx.x * blockDim.x + threadIdx.x;
    if (e >= E) return;
    int s, d;
    if (g_is64) { s = ei[2 * e]; d = ei[2 * E + 2 * e]; }
    else        { s = ei[e];     d = ei[E + e]; }
    g_src[e] = s;
    g_dst[e] = d;
    atomicAdd(&g_deg[d], 1);
}

__global__ void dinv_kernel(int N) {
    int i = blockIdx.x * blockDim.x + threadIdx.x;
    if (i < N) g_dinv[i] = rsqrtf((float)g_deg[i]);
}

// ---------------------------------------------------------------------------
// GEMM: 64-node tile per block (256 threads, 4x4 micro-tile per thread).
// If TRANSFORM: input X is the previous layer's accumulator; apply
//   feat = relu(acc * dinv[node] + bias_prev[k]) while loading the tile.
// Output: g[n][f] = (X@W)[n][f] * dinv[n]   and   acc[n][f] = g[n][f].
// Safe to read+write g_acc in-place: each block reads only the rows it writes,
// and all smem loads complete (syncthreads) before any store.
// ---------------------------------------------------------------------------
template <int FIN, bool TRANSFORM>
__global__ void gemm_kernel(const float* __restrict__ Xin,
                            const float* __restrict__ W,
                            const float* __restrict__ bias_prev,
                            int N) {
    __shared__ float xsT[FIN][68];   // transposed [k][n], padded row
    __shared__ float ws[FIN][H];

    const float* __restrict__ X = TRANSFORM ? (const float*)g_acc : Xin;

    int node0 = blockIdx.x * 64;
    int t = threadIdx.x;

    for (int i = t; i < FIN * H; i += 256) ws[i / H][i % H] = W[i];

    for (int i = t; i < 64 * FIN; i += 256) {
        int n = i / FIN, k = i % FIN;
        int gn = node0 + n;
        float v = 0.f;
        if (gn < N) {
            v = X[gn * FIN + k];
            if (TRANSFORM) v = fmaxf(fmaf(v, g_dinv[gn], bias_prev[k]), 0.f);
        }
        xsT[k][n] = v;
    }
    __syncthreads();

    int tx = t & 15, ty = t >> 4;
    float acc[4][4];
#pragma unroll
    for (int i = 0; i < 4; i++)
#pragma unroll
        for (int j = 0; j < 4; j++) acc[i][j] = 0.f;

#pragma unroll
    for (int k = 0; k < FIN; k++) {
        float4 xv = *(const float4*)&xsT[k][ty * 4];
        float4 wv = *(const float4*)&ws[k][tx * 4];
        float xa[4] = {xv.x, xv.y, xv.z, xv.w};
        float wa[4] = {wv.x, wv.y, wv.z, wv.w};
#pragma unroll
        for (int i = 0; i < 4; i++)
#pragma unroll
            for (int j = 0; j < 4; j++)
                acc[i][j] = fmaf(xa[i], wa[j], acc[i][j]);
    }

#pragma unroll
    for (int i = 0; i < 4; i++) {
        int gn = node0 + ty * 4 + i;
        if (gn < N) {
            float di = g_dinv[gn];
            float4 v = make_float4(acc[i][0] * di, acc[i][1] * di,
                                   acc[i][2] * di, acc[i][3] * di);
            *(float4*)&g_g[gn * H + tx * 4]   = v;
            *(float4*)&g_acc[gn * H + tx * 4] = v;
        }
    }
}

// ---------------------------------------------------------------------------
// Edge scatter: 16 threads per edge, each handles one float4 (4 features).
// Vector reduction (red.global.add.v4.f32, sm_90+) to cut atomic op count 4x.
// ---------------------------------------------------------------------------
__global__ void scatter_kernel(int E) {
    int idx = blockIdx.x * blockDim.x + threadIdx.x;
    int e = idx >> 4;
    if (e >= E) return;
    int lane = idx & 15;
    int s = g_src[e];
    int d = g_dst[e];
    float4 v = __ldg(((const float4*)g_g) + (size_t)s * 16 + lane);
    float4* ap = ((float4*)g_acc) + (size_t)d * 16 + lane;
    asm volatile("red.global.add.v4.f32 [%0], {%1,%2,%3,%4};"
                 :: "l"(ap), "f"(v.x), "f"(v.y), "f"(v.z), "f"(v.w)
                 : "memory");
}

// Layer-3 epilogue fused with mean pooling: colsum[f] = sum_n acc[n][f]*dinv[n]
__global__ void reduce_kernel(int N) {
    int f = threadIdx.x & 63;
    int rows_per_iter = (blockDim.x >> 6) * gridDim.x;
    int row = blockIdx.x * (blockDim.x >> 6) + (threadIdx.x >> 6);
    float sum = 0.f;
    for (int n = row; n < N; n += rows_per_iter)
        sum += g_acc[n * H + f] * g_dinv[n];
    atomicAdd(&g_colsum[f], sum);
}

// out = (colsum/N + b3) . fcW + fcb
__global__ void final_kernel(const float* __restrict__ b3,
                             const float* __restrict__ fcW,
                             const float* __restrict__ fcb,
                             float* __restrict__ out, int N) {
    int f = threadIdx.x;  // 64 threads
    float v = (g_colsum[f] / (float)N + b3[f]) * fcW[f];
#pragma unroll
    for (int o = 16; o > 0; o >>= 1) v += __shfl_down_sync(0xffffffffu, v, o);
    __shared__ float p[2];
    if ((f & 31) == 0) p[f >> 5] = v;
    __syncthreads();
    if (f == 0) out[0] = p[0] + p[1] + fcb[0];
}

extern "C" void kernel_launch(void* const* d_in, const int* in_sizes, int n_in,
                              void* d_out, int out_size) {
    const float* x   = (const float*)d_in[0];
    const void*  ei  = d_in[1];
    const float* W1  = (const float*)d_in[2];
    const float* b1  = (const float*)d_in[3];
    const float* W2  = (const float*)d_in[4];
    const float* b2  = (const float*)d_in[5];
    const float* W3  = (const float*)d_in[6];
    const float* b3  = (const float*)d_in[7];
    const float* fcW = (const float*)d_in[8];
    const float* fcb = (const float*)d_in[9];
    float* out = (float*)d_out;

    int FIN1 = in_sizes[2] / H;      // 10
    int N = in_sizes[0] / FIN1;      // 50000
    int E = in_sizes[1] / 2;         // 800000

    detect_kernel<<<1, 32>>>((const unsigned int*)ei);
    init_kernel<<<(N + 255) / 256, 256>>>(N);
    prep_edges<<<(E + 255) / 256, 256>>>((const int*)ei, E);
    dinv_kernel<<<(N + 255) / 256, 256>>>(N);

    int gblocks = (N + 63) / 64;
    int sblocks = (E * 16 + 255) / 256;

    // Layer 1: x @ W1, no input transform
    gemm_kernel<10, false><<<gblocks, 256>>>(x, W1, nullptr, N);
    scatter_kernel<<<sblocks, 256>>>(E);

    // Layer 2: input = relu(acc1*dinv + b1)
    gemm_kernel<64, true><<<gblocks, 256>>>(nullptr, W2, b1, N);
    scatter_kernel<<<sblocks, 256>>>(E);

    // Layer 3: input = relu(acc2*dinv + b2)
    gemm_kernel<64, true><<<gblocks, 256>>>(nullptr, W3, b2, N);
    scatter_kernel<<<sblocks, 256>>>(E);

    // Epilogue(no relu) + mean pool + FC
    reduce_kernel<<<256, 256>>>(N);
    final_kernel<<<1, 64>>>(b3, fcW, fcb, out, N);
}

// round 2
// speedup vs baseline: 1.4455x; 1.4455x over previous
#include <cuda_runtime.h>
#include <cuda_fp16.h>
#include <cstdint>

#define NMAX 50000
#define EMAX 800000
#define H 64

// Scratch (static device arrays; no dynamic allocation allowed)
__device__ __half g_h[NMAX * H];      // fp16 messages g = (X@W)*dinv_src
__device__ float  g_acc[NMAX * H];    // fp32 accumulator (init = exact self message)
__device__ int    g_cnt[NMAX];        // incoming-edge count (excl self loop)
__device__ float  g_dinv[NMAX];
__device__ int    g_off[NMAX];        // CSR offsets (exclusive prefix of cnt)
__device__ int    g_cur[NMAX];        // fill cursors
__device__ int    g_src[EMAX];
__device__ int    g_dst[EMAX];
__device__ int    g_csr[EMAX];        // CSR-sorted source ids per dst
__device__ int    g_part[64];         // scan partials
__device__ int    g_partoff[64];
__device__ float  g_colsum[H];
__device__ int    g_is64;

// ---------------------------------------------------------------------------
// int64 vs int32 edge_index detection (JAX x64 flag dependent).
// int64 values < 50000 => all odd 32-bit words zero. Warp-parallel.
// ---------------------------------------------------------------------------
__global__ void detect_kernel(const unsigned int* __restrict__ w) {
    int lane = threadIdx.x;
    unsigned int v = w[2 * lane + 1] | w[2 * (lane + 32) + 1];
    int all0 = __all_sync(0xffffffffu, v == 0u);
    if (lane == 0) g_is64 = all0;
}

__global__ void zero_kernel(int N) {
    int i = blockIdx.x * blockDim.x + threadIdx.x;
    if (i < N) g_cnt[i] = 0;
    if (i < H) g_colsum[i] = 0.f;
}

// Decode edges, store, histogram destinations.
__global__ void prep_edges(const int* __restrict__ ei, int E) {
    int e = blockIdx.x * blockDim.x + threadIdx.x;
    if (e >= E) return;
    int s, d;
    if (g_is64) { s = ei[2 * e]; d = ei[2 * E + 2 * e]; }
    else        { s = ei[e];     d = ei[E + e]; }
    g_src[e] = s;
    g_dst[e] = d;
    atomicAdd(&g_cnt[d], 1);
}

// ---- 3-kernel exclusive scan over g_cnt (chunk = 1024 per block) ----------
__global__ void scan_a(int N) {
    int base = blockIdx.x * 1024 + threadIdx.x * 4;
    int s = 0;
#pragma unroll
    for (int j = 0; j < 4; j++) { int idx = base + j; if (idx < N) s += g_cnt[idx]; }
#pragma unroll
    for (int o = 16; o > 0; o >>= 1) s += __shfl_down_sync(0xffffffffu, s, o);
    __shared__ int ws[8];
    if ((threadIdx.x & 31) == 0) ws[threadIdx.x >> 5] = s;
    __syncthreads();
    if (threadIdx.x == 0) {
        int t = 0;
#pragma unroll
        for (int i = 0; i < 8; i++) t += ws[i];
        g_part[blockIdx.x] = t;
    }
}

__global__ void scan_b(int SB) {  // 1 block, 256 threads
    int t = threadIdx.x;
    int v = (t < SB) ? g_part[t] : 0;
    __shared__ int sh[256];
    sh[t] = v;
    __syncthreads();
    for (int o = 1; o < 256; o <<= 1) {
        int add = (t >= o) ? sh[t - o] : 0;
        __syncthreads();
        sh[t] += add;
        __syncthreads();
    }
    if (t < SB) g_partoff[t] = sh[t] - v;  // exclusive
}

__global__ void scan_c(int N) {
    int t = threadIdx.x;
    int base = blockIdx.x * 1024 + t * 4;
    int v[4]; int tsum = 0;
#pragma unroll
    for (int j = 0; j < 4; j++) {
        int idx = base + j;
        v[j] = (idx < N) ? g_cnt[idx] : 0;
        tsum += v[j];
    }
    int lane = t & 31, w = t >> 5;
    int x = tsum;
#pragma unroll
    for (int o = 1; o < 32; o <<= 1) {
        int y = __shfl_up_sync(0xffffffffu, x, o);
        if (lane >= o) x += y;
    }
    __shared__ int wsum[8];
    if (lane == 31) wsum[w] = x;
    __syncthreads();
    if (t == 0) {
        int run = 0;
#pragma unroll
        for (int i = 0; i < 8; i++) { int tmp = wsum[i]; wsum[i] = run; run += tmp; }
    }
    __syncthreads();
    int run = x - tsum + wsum[w] + g_partoff[blockIdx.x];
#pragma unroll
    for (int j = 0; j < 4; j++) {
        int idx = base + j;
        if (idx < N) {
            g_off[idx] = run;
            g_cur[idx] = run;
            g_dinv[idx] = rsqrtf((float)(v[j] + 1));   // +1 = self loop
            run += v[j];
        }
    }
}

__global__ void fill_csr(int E) {
    int e = blockIdx.x * blockDim.x + threadIdx.x;
    if (e >= E) return;
    int d = g_dst[e];
    int pos = atomicAdd(&g_cur[d], 1);
    g_csr[pos] = g_src[e];
}

// ---------------------------------------------------------------------------
// GEMM: 64-node tile per block (256 threads, 4x4 micro-tile).
// TRANSFORM: input = relu(prev_acc * dinv + prev_bias), loaded from g_acc.
// Writes: g_h (fp16 messages, scaled by dinv) and g_acc (fp32 self message).
// ---------------------------------------------------------------------------
template <int FIN, bool TRANSFORM>
__global__ void gemm_kernel(const float* __restrict__ Xin,
                            const float* __restrict__ W,
                            const float* __restrict__ bias_prev,
                            int N) {
    __shared__ float xsT[FIN][68];
    __shared__ float ws[FIN][H];

    const float* __restrict__ X = TRANSFORM ? (const float*)g_acc : Xin;

    int node0 = blockIdx.x * 64;
    int t = threadIdx.x;

    for (int i = t; i < FIN * H; i += 256) ws[i / H][i % H] = W[i];

    for (int i = t; i < 64 * FIN; i += 256) {
        int n = i / FIN, k = i % FIN;
        int gn = node0 + n;
        float v = 0.f;
        if (gn < N) {
            v = X[gn * FIN + k];
            if (TRANSFORM) v = fmaxf(fmaf(v, g_dinv[gn], bias_prev[k]), 0.f);
        }
        xsT[k][n] = v;
    }
    __syncthreads();

    int tx = t & 15, ty = t >> 4;
    float acc[4][4];
#pragma unroll
    for (int i = 0; i < 4; i++)
#pragma unroll
        for (int j = 0; j < 4; j++) acc[i][j] = 0.f;

#pragma unroll
    for (int k = 0; k < FIN; k++) {
        float4 xv = *(const float4*)&xsT[k][ty * 4];
        float4 wv = *(const float4*)&ws[k][tx * 4];
        float xa[4] = {xv.x, xv.y, xv.z, xv.w};
        float wa[4] = {wv.x, wv.y, wv.z, wv.w};
#pragma unroll
        for (int i = 0; i < 4; i++)
#pragma unroll
            for (int j = 0; j < 4; j++)
                acc[i][j] = fmaf(xa[i], wa[j], acc[i][j]);
    }

#pragma unroll
    for (int i = 0; i < 4; i++) {
        int gn = node0 + ty * 4 + i;
        if (gn < N) {
            float di = g_dinv[gn];
            float4 v = make_float4(acc[i][0] * di, acc[i][1] * di,
                                   acc[i][2] * di, acc[i][3] * di);
            *(float4*)&g_acc[gn * H + tx * 4] = v;   // exact self message
            __half2* hp = (__half2*)(g_h + gn * H + tx * 4);
            hp[0] = __floats2half2_rn(v.x, v.y);
            hp[1] = __floats2half2_rn(v.z, v.w);
        }
    }
}

// ---------------------------------------------------------------------------
// CSR aggregation: 8 threads per node, each owns 8 features (16B fp16 chunk).
// acc starts from the exact fp32 self message already in g_acc.
// ---------------------------------------------------------------------------
__global__ void aggregate_kernel(int N) {
    int idx = blockIdx.x * blockDim.x + threadIdx.x;
    int node = idx >> 3;
    if (node >= N) return;
    int lane = idx & 7;

    int start = g_off[node];
    int cnt = g_cnt[node];

    float4 a0 = *(const float4*)(g_acc + (size_t)node * H + lane * 8);
    float4 a1 = *(const float4*)(g_acc + (size_t)node * H + lane * 8 + 4);

    const __half* gh = g_h;
    for (int e = start; e < start + cnt; e++) {
        int s = g_csr[e];
        uint4 raw = __ldg((const uint4*)(gh + (size_t)s * H + lane * 8));
        __half2 h0 = *reinterpret_cast<__half2*>(&raw.x);
        __half2 h1 = *reinterpret_cast<__half2*>(&raw.y);
        __half2 h2 = *reinterpret_cast<__half2*>(&raw.z);
        __half2 h3 = *reinterpret_cast<__half2*>(&raw.w);
        float2 f0 = __half22float2(h0);
        float2 f1 = __half22float2(h1);
        float2 f2 = __half22float2(h2);
        float2 f3 = __half22float2(h3);
        a0.x += f0.x; a0.y += f0.y; a0.z += f1.x; a0.w += f1.y;
        a1.x += f2.x; a1.y += f2.y; a1.z += f3.x; a1.w += f3.y;
    }

    *(float4*)(g_acc + (size_t)node * H + lane * 8)     = a0;
    *(float4*)(g_acc + (size_t)node * H + lane * 8 + 4) = a1;
}

// Layer-3 epilogue fused with mean pooling: colsum[f] = sum_n acc[n][f]*dinv[n]
__global__ void reduce_kernel(int N) {
    int f = threadIdx.x & 63;
    int rows_per_iter = (blockDim.x >> 6) * gridDim.x;
    int row = blockIdx.x * (blockDim.x >> 6) + (threadIdx.x >> 6);
    float sum = 0.f;
    for (int n = row; n < N; n += rows_per_iter)
        sum += g_acc[n * H + f] * g_dinv[n];
    atomicAdd(&g_colsum[f], sum);
}

__global__ void final_kernel(const float* __restrict__ b3,
                             const float* __restrict__ fcW,
                             const float* __restrict__ fcb,
                             float* __restrict__ out, int N) {
    int f = threadIdx.x;  // 64 threads
    float v = (g_colsum[f] / (float)N + b3[f]) * fcW[f];
#pragma unroll
    for (int o = 16; o > 0; o >>= 1) v += __shfl_down_sync(0xffffffffu, v, o);
    __shared__ float p[2];
    if ((f & 31) == 0) p[f >> 5] = v;
    __syncthreads();
    if (f == 0) out[0] = p[0] + p[1] + fcb[0];
}

extern "C" void kernel_launch(void* const* d_in, const int* in_sizes, int n_in,
                              void* d_out, int out_size) {
    const float* x   = (const float*)d_in[0];
    const void*  ei  = d_in[1];
    const float* W1  = (const float*)d_in[2];
    const float* b1  = (const float*)d_in[3];
    const float* W2  = (const float*)d_in[4];
    const float* b2  = (const float*)d_in[5];
    const float* W3  = (const float*)d_in[6];
    const float* b3  = (const float*)d_in[7];
    const float* fcW = (const float*)d_in[8];
    const float* fcb = (const float*)d_in[9];
    float* out = (float*)d_out;

    int FIN1 = in_sizes[2] / H;      // 10
    int N = in_sizes[0] / FIN1;      // 50000
    int E = in_sizes[1] / 2;         // 800000

    int SB = (N + 1023) / 1024;      // scan chunks (<=64)

    detect_kernel<<<1, 32>>>((const unsigned int*)ei);
    zero_kernel<<<(N + 255) / 256, 256>>>(N);
    prep_edges<<<(E + 255) / 256, 256>>>((const int*)ei, E);
    scan_a<<<SB, 256>>>(N);
    scan_b<<<1, 256>>>(SB);
    scan_c<<<SB, 256>>>(N);
    fill_csr<<<(E + 255) / 256, 256>>>(E);

    int gblocks = (N + 63) / 64;
    int ablocks = (N * 8 + 255) / 256;

    gemm_kernel<10, false><<<gblocks, 256>>>(x, W1, nullptr, N);
    aggregate_kernel<<<ablocks, 256>>>(N);

    gemm_kernel<64, true><<<gblocks, 256>>>(nullptr, W2, b1, N);
    aggregate_kernel<<<ablocks, 256>>>(N);

    gemm_kernel<64, true><<<gblocks, 256>>>(nullptr, W3, b2, N);
    aggregate_kernel<<<ablocks, 256>>>(N);

    reduce_kernel<<<256, 256>>>(N);
    final_kernel<<<1, 64>>>(b3, fcW, fcb, out, N);
}